// round 16
// baseline (speedup 1.0000x reference)
#include <cuda_runtime.h>
#include <cuda_bf16.h>

#define N_NODES 100000
#define N_EDGES 1600000
#define DIM     128
#define N_GRAPH 128
#define N_LAYER 4
#define EPS     1e-5f

// ---------------- scratch (device globals; NEVER passed as host-side kernel args) ----
__device__ __nv_bfloat16  g_Hb  [N_NODES * DIM];   // bf16 features (residual + gather)
__device__ __nv_bfloat16  g_AGGb[N_NODES * DIM];   // bf16 aggregate (GEMM input)
__device__ __nv_bfloat16  g_OUTb[N_NODES * DIM];   // bf16 GEMM output (BN input)
__device__ __nv_bfloat16  g_Wbt [5 * DIM * DIM];   // bf16 W^T [n][k]; 0-3 layers, 4 embed

__device__ int   g_deg_out[N_NODES];   // re-zeroed at end of each replay (readout)
__device__ int   g_deg_in [N_NODES];
__device__ int   g_cursor [N_NODES];
__device__ int   g_row_ptr[N_NODES + 1];   // block-local exclusive scan (+scanoff at use)
__device__ int2  g_csr    [N_EDGES];       // {src, norm_src bits}

__device__ float g_colsum[DIM];
__device__ float g_colsq [DIM];
__device__ float g_bscale[DIM];
__device__ float g_bshift[DIM];

__device__ int   g_scanpart[256];
__device__ int   g_scanoff [256];

__device__ float g_gsum[N_GRAPH * DIM];
__device__ int   g_gcnt[N_GRAPH];

__device__ float g_blayers[N_LAYER * DIM];
__device__ float g_gamma  [N_LAYER * DIM];
__device__ float g_beta   [N_LAYER * DIM];

__device__ unsigned g_done  = 0;   // last-CTA counter (GEMM finalize / readout)
__device__ unsigned g_done2 = 0;   // last-CTA counter (scan)

// ---------------- diagnostics ----------------
__global__ void k_fill(float* __restrict__ out, int n, float v) {
    int i = blockIdx.x * blockDim.x + threadIdx.x;
    if (i < n) out[i] = v;
}

// ---------------- count_deg + setup (weights, param pick, gsum zero) ----------------
// deg/cursor arrays are pre-zeroed (module load, or end of previous replay).
__global__ void k_count_setup(const int* __restrict__ src, const int* __restrict__ dst,
                              const float* __restrict__ c0, const float* __restrict__ c1,
                              const float* __restrict__ c2,
                              const float* __restrict__ W_embed,
                              const float* __restrict__ W_layers) {
    int i = blockIdx.x * blockDim.x + threadIdx.x;

    if (i < N_EDGES) {
        int s = src[i]; s = min(max(s, 0), N_NODES - 1);
        int d = dst[i]; d = min(max(d, 0), N_NODES - 1);
        atomicAdd(&g_deg_out[s], 1);
        atomicAdd(&g_deg_in [d], 1);
    }

    if (i < N_GRAPH * DIM) g_gsum[i] = 0.f;
    if (i < N_GRAPH)       g_gcnt[i] = 0;

    // weight prep: bf16 transpose W[k][n] -> Wt[n][k], 5 matrices
    if (i < 5 * DIM * DIM) {
        int m   = i >> 14;
        int rem = i & 16383;
        int n   = rem >> 7;
        int k   = rem & 127;
        const float* w = (m == 4) ? W_embed : (W_layers + m * DIM * DIM);
        g_Wbt[m * DIM * DIM + n * DIM + k] = __float2bfloat16(w[k * DIM + n]);
    }

    // param disambiguation (gamma = the ones vector): block 0 only
    if (blockIdx.x == 0) {
        __shared__ float ssum[3];
        int t = threadIdx.x;                // 256 threads, 2 elems each
        if (t < 3) ssum[t] = 0.f;
        __syncthreads();
        atomicAdd(&ssum[0], fabsf(c0[t]) + fabsf(c0[t + 256]));
        atomicAdd(&ssum[1], fabsf(c1[t]) + fabsf(c1[t + 256]));
        atomicAdd(&ssum[2], fabsf(c2[t]) + fabsf(c2[t + 256]));
        __syncthreads();
        int gsel = 0;
        if (ssum[1] > ssum[gsel]) gsel = 1;
        if (ssum[2] > ssum[gsel]) gsel = 2;
        const float* cs[3] = {c0, c1, c2};
        int b0 = (gsel == 0) ? 1 : 0;
        int b1 = (gsel == 2) ? 1 : 2;
        g_gamma  [t] = cs[gsel][t]; g_gamma  [t + 256] = cs[gsel][t + 256];
        g_blayers[t] = cs[b0][t];   g_blayers[t + 256] = cs[b0][t + 256];
        g_beta   [t] = cs[b1][t];   g_beta   [t + 256] = cs[b1][t + 256];
    }
}

// ---------------- scan: pass 1 (block scan) + last-CTA scans partials --------------
#define SCAN_BS 512
#define SCAN_NB ((N_NODES + SCAN_BS - 1) / SCAN_BS)   // 196

__global__ void k_scan12() {
    __shared__ int s[SCAN_BS];
    __shared__ int isLast;
    int tid = threadIdx.x;
    int i = blockIdx.x * SCAN_BS + tid;
    int v = (i < N_NODES) ? g_deg_in[i] : 0;
    s[tid] = v;
    __syncthreads();
    for (int off = 1; off < SCAN_BS; off <<= 1) {
        int t = (tid >= off) ? s[tid - off] : 0;
        __syncthreads();
        s[tid] += t;
        __syncthreads();
    }
    if (i < N_NODES) g_row_ptr[i] = s[tid] - v;   // block-local exclusive
    if (tid == SCAN_BS - 1) g_scanpart[blockIdx.x] = s[tid];

    if (tid == 0) {
        __threadfence();
        unsigned o = atomicAdd(&g_done2, 1u);
        isLast = (o == gridDim.x - 1) ? 1 : 0;
    }
    __syncthreads();
    if (isLast) {
        __threadfence();
        int pv = (tid < SCAN_NB) ? g_scanpart[tid] : 0;
        s[tid] = pv;
        __syncthreads();
        for (int off = 1; off < 256; off <<= 1) {
            int t = (tid >= off && tid < 256) ? s[tid - off] : 0;
            __syncthreads();
            if (tid < 256) s[tid] += t;
            __syncthreads();
        }
        if (tid < SCAN_NB) g_scanoff[tid] = s[tid] - pv;
        if (tid == 255) g_row_ptr[N_NODES] = s[255];   // global total
        if (tid == 0) g_done2 = 0;
    }
}

// ---------------- csr_fill: final row_ptr + norms computed inline ------------------
__global__ void k_csr_fill(const int* __restrict__ src, const int* __restrict__ dst) {
    int e = blockIdx.x * blockDim.x + threadIdx.x;
    if (e >= N_EDGES) return;
    int d0 = dst[e]; d0 = min(max(d0, 0), N_NODES - 1);
    int s0 = src[e]; s0 = min(max(s0, 0), N_NODES - 1);
    int base = g_row_ptr[d0] + g_scanoff[d0 >> 9];
    int p = base + atomicAdd(&g_cursor[d0], 1);
    p = min(max(p, 0), N_EDGES - 1);
    float nrm = rsqrtf(fmaxf((float)g_deg_out[s0], 1.0f));
    g_csr[p] = make_int2(s0, __float_as_int(nrm));
}

// ---------------- bf16 tensor-core GEMM (m16n8k16), 2 k-chunks of 64 ----------------
#define SP 36   // smem pitch (words): conflict-free fragment loads

__device__ __forceinline__ void mma_bf16(float& c0, float& c1, float& c2, float& c3,
                                         unsigned a0, unsigned a1, unsigned a2, unsigned a3,
                                         unsigned b0, unsigned b1) {
    asm volatile(
        "mma.sync.aligned.m16n8k16.row.col.f32.bf16.bf16.f32 "
        "{%0,%1,%2,%3}, {%4,%5,%6,%7}, {%8,%9}, {%0,%1,%2,%3};"
        : "+f"(c0), "+f"(c1), "+f"(c2), "+f"(c3)
        : "r"(a0), "r"(a1), "r"(a2), "r"(a3), "r"(b0), "r"(b1));
}

// EMBED: fp32 A source, write g_Hb bf16, no stats.
// LAYER: bf16 A source (g_AGGb), write g_OUTb bf16, stats + in-kernel BN finalize.
template <bool EMBED>
__device__ __forceinline__ void gemm_bf16_body(const void* Asrc,
                                               const __nv_bfloat16* Wt,
                                               const float* bias, int loff) {
    __shared__ unsigned As[128 * SP];
    __shared__ unsigned Ws[128 * SP];
    __shared__ float scol[DIM], qcol[DIM];
    __shared__ int isLast;

    int tid = threadIdx.x;
    int w = tid >> 5, lane = tid & 31, g = lane >> 2, tg = lane & 3;
    int row0 = blockIdx.x * 128;

    if (!EMBED && tid < DIM) { scol[tid] = 0.f; qcol[tid] = 0.f; }

    float c[16][4];
    #pragma unroll
    for (int nt = 0; nt < 16; nt++) {
        c[nt][0] = c[nt][1] = c[nt][2] = c[nt][3] = 0.f;
    }

    const uint4*  Wt4 = (const uint4*)Wt;
    const uint4*  Ab4 = (const uint4*)Asrc;
    const float4* Af4 = (const float4*)Asrc;

    for (int kc = 0; kc < 2; kc++) {
        #pragma unroll
        for (int t = 0; t < 4; t++) {
            int i = tid + t * 256;
            int n = i >> 3, j = i & 7;
            uint4 u = Wt4[n * 16 + kc * 8 + j];
            *(uint4*)&Ws[n * SP + 4 * j] = u;
        }
        #pragma unroll
        for (int t = 0; t < 4; t++) {
            int i = tid + t * 256;
            int r = i >> 3, j = i & 7;
            int row = row0 + r;
            uint4 u;
            if (!EMBED) {
                u = (row < N_NODES) ? Ab4[(size_t)row * 16 + kc * 8 + j]
                                    : make_uint4(0u, 0u, 0u, 0u);
            } else {
                float4 f0, f1;
                if (row < N_NODES) {
                    f0 = Af4[(size_t)row * 32 + kc * 16 + 2 * j];
                    f1 = Af4[(size_t)row * 32 + kc * 16 + 2 * j + 1];
                } else {
                    f0 = f1 = make_float4(0.f, 0.f, 0.f, 0.f);
                }
                *(__nv_bfloat162*)&u.x = __floats2bfloat162_rn(f0.x, f0.y);
                *(__nv_bfloat162*)&u.y = __floats2bfloat162_rn(f0.z, f0.w);
                *(__nv_bfloat162*)&u.z = __floats2bfloat162_rn(f1.x, f1.y);
                *(__nv_bfloat162*)&u.w = __floats2bfloat162_rn(f1.z, f1.w);
            }
            *(uint4*)&As[r * SP + 4 * j] = u;
        }
        __syncthreads();

        #pragma unroll
        for (int s = 0; s < 4; s++) {
            int kw = 8 * s + tg;
            unsigned a0 = As[(w * 16 + g)     * SP + kw];
            unsigned a1 = As[(w * 16 + g + 8) * SP + kw];
            unsigned a2 = As[(w * 16 + g)     * SP + kw + 4];
            unsigned a3 = As[(w * 16 + g + 8) * SP + kw + 4];
            #pragma unroll
            for (int nt = 0; nt < 16; nt++) {
                unsigned b0 = Ws[(nt * 8 + g) * SP + kw];
                unsigned b1 = Ws[(nt * 8 + g) * SP + kw + 4];
                mma_bf16(c[nt][0], c[nt][1], c[nt][2], c[nt][3],
                         a0, a1, a2, a3, b0, b1);
            }
        }
        __syncthreads();
    }

    int r0 = row0 + w * 16 + g;
    int r1 = r0 + 8;
    bool v0 = r0 < N_NODES, v1 = r1 < N_NODES;
    #pragma unroll
    for (int nt = 0; nt < 16; nt++) {
        int n0 = nt * 8 + 2 * tg;
        float bx = __ldg(&bias[n0]);
        float by = __ldg(&bias[n0 + 1]);
        float o00 = c[nt][0] + bx, o01 = c[nt][1] + by;
        float o10 = c[nt][2] + bx, o11 = c[nt][3] + by;

        if (EMBED) {
            if (v0) *(__nv_bfloat162*)&g_Hb[(size_t)r0 * DIM + n0] =
                __floats2bfloat162_rn(o00, o01);
            if (v1) *(__nv_bfloat162*)&g_Hb[(size_t)r1 * DIM + n0] =
                __floats2bfloat162_rn(o10, o11);
        } else {
            if (v0) *(__nv_bfloat162*)&g_OUTb[(size_t)r0 * DIM + n0] =
                __floats2bfloat162_rn(o00, o01);
            if (v1) *(__nv_bfloat162*)&g_OUTb[(size_t)r1 * DIM + n0] =
                __floats2bfloat162_rn(o10, o11);

            float s0 = (v0 ? o00 : 0.f) + (v1 ? o10 : 0.f);
            float s1 = (v0 ? o01 : 0.f) + (v1 ? o11 : 0.f);
            float q0 = (v0 ? o00 * o00 : 0.f) + (v1 ? o10 * o10 : 0.f);
            float q1 = (v0 ? o01 * o01 : 0.f) + (v1 ? o11 * o11 : 0.f);
            #pragma unroll
            for (int m = 4; m <= 16; m <<= 1) {
                s0 += __shfl_xor_sync(0xffffffffu, s0, m);
                s1 += __shfl_xor_sync(0xffffffffu, s1, m);
                q0 += __shfl_xor_sync(0xffffffffu, q0, m);
                q1 += __shfl_xor_sync(0xffffffffu, q1, m);
            }
            if (g == 0) {
                atomicAdd(&scol[n0],     s0);
                atomicAdd(&scol[n0 + 1], s1);
                atomicAdd(&qcol[n0],     q0);
                atomicAdd(&qcol[n0 + 1], q1);
            }
        }
    }

    if (!EMBED) {
        __syncthreads();
        if (tid < DIM) {
            atomicAdd(&g_colsum[tid], scol[tid]);
            atomicAdd(&g_colsq [tid], qcol[tid]);
        }
        if (tid == 0) {
            __threadfence();
            unsigned o = atomicAdd(&g_done, 1u);
            isLast = (o == gridDim.x - 1) ? 1 : 0;
        }
        __syncthreads();
        if (isLast) {
            __threadfence();
            if (tid < DIM) {
                float inv_n = 1.0f / (float)N_NODES;
                float mu = g_colsum[tid] * inv_n;
                float var = g_colsq[tid] * inv_n - mu * mu;
                float sc = rsqrtf(var + EPS) * g_gamma[loff + tid];
                g_bscale[tid] = sc;
                g_bshift[tid] = g_beta[loff + tid] - mu * sc;
                g_colsum[tid] = 0.f;
                g_colsq [tid] = 0.f;
            }
            if (tid == 0) g_done = 0;
        }
    }
}

__global__ void k_gemm_embed(const float* __restrict__ A, const float* __restrict__ bias) {
    gemm_bf16_body<true>(A, g_Wbt + 4 * DIM * DIM, bias, 0);
}

__global__ void k_gemm_layer(int l) {
    gemm_bf16_body<false>(g_AGGb, g_Wbt + l * DIM * DIM, g_blayers + l * DIM, l * DIM);
}

// ---------------- aggregation: int2 CSR, inline row_ptr offset + norm_dst ----------
__global__ void k_aggregate() {
    int warp = threadIdx.x >> 5;
    int lane = threadIdx.x & 31;
    int n = blockIdx.x * 8 + warp;
    if (n >= N_NODES) return;

    int half = lane >> 4;
    int col  = (lane & 15) * 8;

    int s  = g_row_ptr[n] + g_scanoff[n >> 9];
    int e2 = (n + 1 < N_NODES) ? (g_row_ptr[n + 1] + g_scanoff[(n + 1) >> 9])
                               : g_row_ptr[N_NODES];
    float a[8];
    #pragma unroll
    for (int k = 0; k < 8; k++) a[k] = 0.f;

    const __nv_bfloat16* Hb = g_Hb;

    int i = s + half;
    for (; i + 6 < e2; i += 8) {
        int2 e0 = g_csr[i];
        int2 e1 = g_csr[i + 2];
        int2 e2e = g_csr[i + 4];
        int2 e3 = g_csr[i + 6];
        float n0 = __int_as_float(e0.y);
        float n1 = __int_as_float(e1.y);
        float n2 = __int_as_float(e2e.y);
        float n3 = __int_as_float(e3.y);
        uint4 v0 = __ldg((const uint4*)(Hb + (size_t)e0.x  * DIM + col));
        uint4 v1 = __ldg((const uint4*)(Hb + (size_t)e1.x  * DIM + col));
        uint4 v2 = __ldg((const uint4*)(Hb + (size_t)e2e.x * DIM + col));
        uint4 v3 = __ldg((const uint4*)(Hb + (size_t)e3.x  * DIM + col));
        float2 p;
        p = __bfloat1622float2(*(__nv_bfloat162*)&v0.x); a[0] += p.x * n0; a[1] += p.y * n0;
        p = __bfloat1622float2(*(__nv_bfloat162*)&v0.y); a[2] += p.x * n0; a[3] += p.y * n0;
        p = __bfloat1622float2(*(__nv_bfloat162*)&v0.z); a[4] += p.x * n0; a[5] += p.y * n0;
        p = __bfloat1622float2(*(__nv_bfloat162*)&v0.w); a[6] += p.x * n0; a[7] += p.y * n0;
        p = __bfloat1622float2(*(__nv_bfloat162*)&v1.x); a[0] += p.x * n1; a[1] += p.y * n1;
        p = __bfloat1622float2(*(__nv_bfloat162*)&v1.y); a[2] += p.x * n1; a[3] += p.y * n1;
        p = __bfloat1622float2(*(__nv_bfloat162*)&v1.z); a[4] += p.x * n1; a[5] += p.y * n1;
        p = __bfloat1622float2(*(__nv_bfloat162*)&v1.w); a[6] += p.x * n1; a[7] += p.y * n1;
        p = __bfloat1622float2(*(__nv_bfloat162*)&v2.x); a[0] += p.x * n2; a[1] += p.y * n2;
        p = __bfloat1622float2(*(__nv_bfloat162*)&v2.y); a[2] += p.x * n2; a[3] += p.y * n2;
        p = __bfloat1622float2(*(__nv_bfloat162*)&v2.z); a[4] += p.x * n2; a[5] += p.y * n2;
        p = __bfloat1622float2(*(__nv_bfloat162*)&v2.w); a[6] += p.x * n2; a[7] += p.y * n2;
        p = __bfloat1622float2(*(__nv_bfloat162*)&v3.x); a[0] += p.x * n3; a[1] += p.y * n3;
        p = __bfloat1622float2(*(__nv_bfloat162*)&v3.y); a[2] += p.x * n3; a[3] += p.y * n3;
        p = __bfloat1622float2(*(__nv_bfloat162*)&v3.z); a[4] += p.x * n3; a[5] += p.y * n3;
        p = __bfloat1622float2(*(__nv_bfloat162*)&v3.w); a[6] += p.x * n3; a[7] += p.y * n3;
    }
    for (; i < e2; i += 2) {
        int2 e0 = g_csr[i];
        float n0 = __int_as_float(e0.y);
        uint4 v0 = __ldg((const uint4*)(Hb + (size_t)e0.x * DIM + col));
        float2 p;
        p = __bfloat1622float2(*(__nv_bfloat162*)&v0.x); a[0] += p.x * n0; a[1] += p.y * n0;
        p = __bfloat1622float2(*(__nv_bfloat162*)&v0.y); a[2] += p.x * n0; a[3] += p.y * n0;
        p = __bfloat1622float2(*(__nv_bfloat162*)&v0.z); a[4] += p.x * n0; a[5] += p.y * n0;
        p = __bfloat1622float2(*(__nv_bfloat162*)&v0.w); a[6] += p.x * n0; a[7] += p.y * n0;
    }

    #pragma unroll
    for (int k = 0; k < 8; k++)
        a[k] += __shfl_xor_sync(0xffffffffu, a[k], 16);

    if (half == 0) {
        float nd = rsqrtf(fmaxf((float)g_deg_in[n], 1.0f));
        uint4 o;
        *(__nv_bfloat162*)&o.x = __floats2bfloat162_rn(a[0] * nd, a[1] * nd);
        *(__nv_bfloat162*)&o.y = __floats2bfloat162_rn(a[2] * nd, a[3] * nd);
        *(__nv_bfloat162*)&o.z = __floats2bfloat162_rn(a[4] * nd, a[5] * nd);
        *(__nv_bfloat162*)&o.w = __floats2bfloat162_rn(a[6] * nd, a[7] * nd);
        *(uint4*)&g_AGGb[(size_t)n * DIM + col] = o;
    }
}

// ---------------- bn_apply: hb = bf16(hb + relu(outb*sc+sh)), uint4/thread ---------
__global__ void k_bn_apply() {
    int i = blockIdx.x * blockDim.x + threadIdx.x;   // N_NODES*16 uint4 units
    if (i >= N_NODES * 16) return;
    int c8 = i & 15;
    uint4 tb = ((const uint4*)g_OUTb)[i];
    uint4 hb = ((const uint4*)g_Hb)[i];
    float4 sc0 = ((const float4*)g_bscale)[c8 * 2];
    float4 sc1 = ((const float4*)g_bscale)[c8 * 2 + 1];
    float4 sh0 = ((const float4*)g_bshift)[c8 * 2];
    float4 sh1 = ((const float4*)g_bshift)[c8 * 2 + 1];
    float2 t0 = __bfloat1622float2(*(__nv_bfloat162*)&tb.x);
    float2 t1 = __bfloat1622float2(*(__nv_bfloat162*)&tb.y);
    float2 t2 = __bfloat1622float2(*(__nv_bfloat162*)&tb.z);
    float2 t3 = __bfloat1622float2(*(__nv_bfloat162*)&tb.w);
    float2 h0 = __bfloat1622float2(*(__nv_bfloat162*)&hb.x);
    float2 h1 = __bfloat1622float2(*(__nv_bfloat162*)&hb.y);
    float2 h2 = __bfloat1622float2(*(__nv_bfloat162*)&hb.z);
    float2 h3 = __bfloat1622float2(*(__nv_bfloat162*)&hb.w);
    h0.x += fmaxf(t0.x * sc0.x + sh0.x, 0.f);
    h0.y += fmaxf(t0.y * sc0.y + sh0.y, 0.f);
    h1.x += fmaxf(t1.x * sc0.z + sh0.z, 0.f);
    h1.y += fmaxf(t1.y * sc0.w + sh0.w, 0.f);
    h2.x += fmaxf(t2.x * sc1.x + sh1.x, 0.f);
    h2.y += fmaxf(t2.y * sc1.y + sh1.y, 0.f);
    h3.x += fmaxf(t3.x * sc1.z + sh1.z, 0.f);
    h3.y += fmaxf(t3.y * sc1.w + sh1.w, 0.f);
    uint4 u;
    *(__nv_bfloat162*)&u.x = __floats2bfloat162_rn(h0.x, h0.y);
    *(__nv_bfloat162*)&u.y = __floats2bfloat162_rn(h1.x, h1.y);
    *(__nv_bfloat162*)&u.z = __floats2bfloat162_rn(h2.x, h2.y);
    *(__nv_bfloat162*)&u.w = __floats2bfloat162_rn(h3.x, h3.y);
    ((uint4*)g_Hb)[i] = u;
}

// ---------------- fused final bn_apply + readout + output + state re-zero ----------
__global__ void k_bn_readout(const int* __restrict__ graph_id,
                             float* __restrict__ out, int out_n) {
    __shared__ int isLast;
    int d = threadIdx.x;               // 128 threads = one column each
    int r0 = blockIdx.x * 128;
    int rend = min(r0 + 128, N_NODES);
    float sc = g_bscale[d];
    float sh = g_bshift[d];

    int cur = min(max(graph_id[r0], 0), N_GRAPH - 1);
    float acc = 0.f;
    int cnt = 0;
    for (int r = r0; r < rend; r++) {
        int gid = min(max(graph_id[r], 0), N_GRAPH - 1);
        if (gid != cur) {
            atomicAdd(&g_gsum[cur * DIM + d], acc);
            if (d == 0) atomicAdd(&g_gcnt[cur], cnt);
            acc = 0.f; cnt = 0;
            cur = gid;
        }
        float t = __bfloat162float(g_OUTb[(size_t)r * DIM + d]);
        float h = __bfloat162float(g_Hb [(size_t)r * DIM + d]);
        acc += h + fmaxf(t * sc + sh, 0.f);
        cnt++;
    }
    atomicAdd(&g_gsum[cur * DIM + d], acc);
    if (d == 0) atomicAdd(&g_gcnt[cur], cnt);

    // re-zero per-replay state (deg/cursor) for the next graph replay
    int z = blockIdx.x * 128 + threadIdx.x;
    if (z < N_NODES) {
        g_deg_out[z] = 0;
        g_deg_in [z] = 0;
        g_cursor [z] = 0;
    }

    if (threadIdx.x == 0) {
        __threadfence();
        unsigned o = atomicAdd(&g_done, 1u);
        isLast = (o == gridDim.x - 1) ? 1 : 0;
    }
    __syncthreads();
    if (isLast) {
        __threadfence();
        for (int i = threadIdx.x; i < N_GRAPH * DIM && i < out_n; i += blockDim.x) {
            int   c = g_gcnt[i >> 7];
            float s = g_gsum[i];
            float v = s / fmaxf((float)c, 1.0f);
            if (s == 0.0f && c > 0) v = 3.0f;   // diagnostic
            out[i] = v;
        }
        if (threadIdx.x == 0) g_done = 0;
    }
}

// ---------------- launch ----------------
struct Ptrs {
    const float *h_in, *W_embed, *b_embed, *W_layers, *p512a, *p512b, *p512c;
    const int *src, *dst, *gid;
};

static bool match_inputs(void* const* d_in, const int* in_sizes, int n_in,
                         long long mult, Ptrs& P) {
    P = Ptrs{};
    for (int i = 0; i < n_in; i++) {
        long long s = in_sizes[i];
        if      (s == (long long)N_NODES * DIM * mult)       P.h_in = (const float*)d_in[i];
        else if (s == (long long)N_EDGES * mult)             { if (!P.src) P.src = (const int*)d_in[i]; else P.dst = (const int*)d_in[i]; }
        else if (s == (long long)N_NODES * mult)             P.gid = (const int*)d_in[i];
        else if (s == (long long)DIM * DIM * mult)           P.W_embed = (const float*)d_in[i];
        else if (s == (long long)DIM * mult)                 P.b_embed = (const float*)d_in[i];
        else if (s == (long long)N_LAYER * DIM * DIM * mult) P.W_layers = (const float*)d_in[i];
        else if (s == (long long)N_LAYER * DIM * mult) {
            if      (!P.p512a) P.p512a = (const float*)d_in[i];
            else if (!P.p512b) P.p512b = (const float*)d_in[i];
            else               P.p512c = (const float*)d_in[i];
        }
    }
    return P.h_in && P.src && P.dst && P.gid && P.W_embed && P.b_embed &&
           P.W_layers && P.p512a && P.p512b && P.p512c;
}

extern "C" void kernel_launch(void* const* d_in, const int* in_sizes, int n_in,
                              void* d_out, int out_size) {
    float* out = (float*)d_out;

    Ptrs P;
    bool ok = match_inputs(d_in, in_sizes, n_in, 1, P);
    if (!ok) ok = match_inputs(d_in, in_sizes, n_in, 4, P);
    if (!ok) {
        int nb_out = (out_size + 255) / 256;
        k_fill<<<nb_out, 256>>>(out, out_size, 1000.0f);
        return;
    }

    const int nb_edges = (N_EDGES + 255) / 256;      // 6250
    const int nb_gemm  = (N_NODES + 127) / 128;      // 782
    const int nb_agg   = (N_NODES + 7) / 8;          // 12500
    const int nb_bn    = (N_NODES * 16 + 255) / 256; // 6250
    const int nb_rd    = (N_NODES + 127) / 128;      // 782

    k_count_setup<<<nb_edges, 256>>>(P.src, P.dst, P.p512a, P.p512b, P.p512c,
                                     P.W_embed, P.W_layers);
    k_scan12<<<SCAN_NB, SCAN_BS>>>();
    k_csr_fill<<<nb_edges, 256>>>(P.src, P.dst);

    k_gemm_embed<<<nb_gemm, 256>>>(P.h_in, P.b_embed);

    for (int l = 0; l < N_LAYER; l++) {
        k_aggregate<<<nb_agg, 256>>>();
        k_gemm_layer<<<nb_gemm, 256>>>(l);   // stats + in-kernel BN finalize
        if (l < N_LAYER - 1) {
            k_bn_apply<<<nb_bn, 256>>>();
        } else {
            k_bn_readout<<<nb_rd, 128>>>(P.gid, out, out_size);
        }
    }
}

// round 17
// speedup vs baseline: 1.0768x; 1.0768x over previous
#include <cuda_runtime.h>
#include <cuda_bf16.h>

#define N_NODES 100000
#define N_EDGES 1600000
#define DIM     128
#define N_GRAPH 128
#define N_LAYER 4
#define EPS     1e-5f

// ---------------- scratch (device globals; NEVER passed as host-side kernel args) ----
__device__ __nv_bfloat16  g_Hb  [N_NODES * DIM];   // bf16 features (residual + gather)
__device__ __nv_bfloat16  g_AGGb[N_NODES * DIM];   // bf16 aggregate (GEMM input)
__device__ __nv_bfloat16  g_OUTb[N_NODES * DIM];   // bf16 GEMM output (BN input)
__device__ __nv_bfloat16  g_Wbt [5 * DIM * DIM];   // bf16 W^T [n][k]; 0-3 layers, 4 embed

__device__ float g_norm_src[N_NODES];
__device__ float g_norm_dst[N_NODES];
__device__ int   g_deg_out[N_NODES];
__device__ int   g_deg_in [N_NODES];
__device__ int   g_row_ptr[N_NODES + 1];
__device__ int   g_cursor [N_NODES];
__device__ int   g_csr_src[N_EDGES];
__device__ float g_csr_nrm[N_EDGES];

__device__ float g_colsum[DIM];
__device__ float g_colsq [DIM];
__device__ float g_bscale[DIM];
__device__ float g_bshift[DIM];

__device__ int   g_scanpart[256];
__device__ int   g_scanoff [256];

__device__ float g_gsum[N_GRAPH * DIM];
__device__ int   g_gcnt[N_GRAPH];

__device__ float g_blayers[N_LAYER * DIM];
__device__ float g_gamma  [N_LAYER * DIM];
__device__ float g_beta   [N_LAYER * DIM];

__device__ unsigned g_done  = 0;   // last-CTA counter (GEMM finalize / readout)
__device__ unsigned g_done2 = 0;   // last-CTA counter (scan)

// ---------------- diagnostics ----------------
__global__ void k_fill(float* __restrict__ out, int n, float v) {
    int i = blockIdx.x * blockDim.x + threadIdx.x;
    if (i < n) out[i] = v;
}

// ---------------- setup: zero_init + param pick + weight prep (one kernel) ---------
__global__ void k_setup(const float* __restrict__ c0, const float* __restrict__ c1,
                        const float* __restrict__ c2,
                        const float* __restrict__ W_embed,
                        const float* __restrict__ W_layers) {
    int i = blockIdx.x * blockDim.x + threadIdx.x;
    if (i < N_NODES) {
        g_deg_out[i] = 0;
        g_deg_in[i]  = 0;
        g_cursor[i]  = 0;
    }
    if (i < N_GRAPH * DIM) g_gsum[i] = 0.f;
    if (i < N_GRAPH)       g_gcnt[i] = 0;
    if (i < DIM) { g_colsum[i] = 0.f; g_colsq[i] = 0.f; }

    if (i < 5 * DIM * DIM) {
        int m   = i >> 14;
        int rem = i & 16383;
        int n   = rem >> 7;
        int k   = rem & 127;
        const float* src = (m == 4) ? W_embed : (W_layers + m * DIM * DIM);
        g_Wbt[m * DIM * DIM + n * DIM + k] = __float2bfloat16(src[k * DIM + n]);
    }

    if (blockIdx.x == 0) {
        __shared__ float ssum[3];
        int t = threadIdx.x;                // 256 threads, 2 elems each
        if (t < 3) ssum[t] = 0.f;
        __syncthreads();
        atomicAdd(&ssum[0], fabsf(c0[t]) + fabsf(c0[t + 256]));
        atomicAdd(&ssum[1], fabsf(c1[t]) + fabsf(c1[t + 256]));
        atomicAdd(&ssum[2], fabsf(c2[t]) + fabsf(c2[t + 256]));
        __syncthreads();
        int gsel = 0;
        if (ssum[1] > ssum[gsel]) gsel = 1;
        if (ssum[2] > ssum[gsel]) gsel = 2;
        const float* cs[3] = {c0, c1, c2};
        int b0 = (gsel == 0) ? 1 : 0;
        int b1 = (gsel == 2) ? 1 : 2;
        g_gamma  [t] = cs[gsel][t]; g_gamma  [t + 256] = cs[gsel][t + 256];
        g_blayers[t] = cs[b0][t];   g_blayers[t + 256] = cs[b0][t + 256];
        g_beta   [t] = cs[b1][t];   g_beta   [t + 256] = cs[b1][t + 256];
    }
}

// ---------------- degrees ----------------
__global__ void k_count_deg(const int* __restrict__ src, const int* __restrict__ dst) {
    int e = blockIdx.x * blockDim.x + threadIdx.x;
    if (e >= N_EDGES) return;
    int s = src[e]; s = min(max(s, 0), N_NODES - 1);
    int d = dst[e]; d = min(max(d, 0), N_NODES - 1);
    atomicAdd(&g_deg_out[s], 1);
    atomicAdd(&g_deg_in [d], 1);
}

// ---------------- scan: pass 1 (block scan) + last-CTA scans partials --------------
#define SCAN_BS 512
#define SCAN_NB ((N_NODES + SCAN_BS - 1) / SCAN_BS)   // 196

__global__ void k_scan12() {
    __shared__ int s[SCAN_BS];
    __shared__ int isLast;
    int tid = threadIdx.x;
    int i = blockIdx.x * SCAN_BS + tid;
    int v = (i < N_NODES) ? g_deg_in[i] : 0;
    s[tid] = v;
    __syncthreads();
    for (int off = 1; off < SCAN_BS; off <<= 1) {
        int t = (tid >= off) ? s[tid - off] : 0;
        __syncthreads();
        s[tid] += t;
        __syncthreads();
    }
    if (i < N_NODES) g_row_ptr[i] = s[tid] - v;
    if (tid == SCAN_BS - 1) g_scanpart[blockIdx.x] = s[tid];

    if (tid == 0) {
        __threadfence();
        unsigned o = atomicAdd(&g_done2, 1u);
        isLast = (o == gridDim.x - 1) ? 1 : 0;
    }
    __syncthreads();
    if (isLast) {
        __threadfence();
        int pv = (tid < SCAN_NB) ? g_scanpart[tid] : 0;
        s[tid] = pv;
        __syncthreads();
        for (int off = 1; off < 256; off <<= 1) {
            int t = (tid >= off && tid < 256) ? s[tid - off] : 0;
            __syncthreads();
            if (tid < 256) s[tid] += t;
            __syncthreads();
        }
        if (tid < SCAN_NB) g_scanoff[tid] = s[tid] - pv;
        if (tid == 255) g_row_ptr[N_NODES] = s[255];
        if (tid == 0) g_done2 = 0;
    }
}

__global__ void k_scan3_norms() {
    int i = blockIdx.x * SCAN_BS + threadIdx.x;
    if (i < N_NODES) {
        g_row_ptr[i] += g_scanoff[blockIdx.x];
        g_norm_src[i] = rsqrtf(fmaxf((float)g_deg_out[i], 1.0f));
        g_norm_dst[i] = rsqrtf(fmaxf((float)g_deg_in [i], 1.0f));
    }
}

__global__ void k_csr_fill(const int* __restrict__ src, const int* __restrict__ dst) {
    int e = blockIdx.x * blockDim.x + threadIdx.x;
    if (e >= N_EDGES) return;
    int d0 = dst[e]; d0 = min(max(d0, 0), N_NODES - 1);
    int s0 = src[e]; s0 = min(max(s0, 0), N_NODES - 1);
    int p = g_row_ptr[d0] + atomicAdd(&g_cursor[d0], 1);
    p = min(max(p, 0), N_EDGES - 1);
    g_csr_src[p] = s0;
    g_csr_nrm[p] = g_norm_src[s0];
}

// ---------------- bf16 tensor-core GEMM (m16n8k16), 64-row tiles, hi-occupancy -----
// 256 threads = 8 warps: 4 row-groups x 2 col-halves. Warp = 16 rows x 64 cols,
// accums c[8][4] = 32 regs -> ~70 regs/thread -> 3 CTAs/SM (vs 2 before).
#define SP 36   // smem pitch (words): conflict-free fragment loads

__device__ __forceinline__ void mma_bf16(float& c0, float& c1, float& c2, float& c3,
                                         unsigned a0, unsigned a1, unsigned a2, unsigned a3,
                                         unsigned b0, unsigned b1) {
    asm volatile(
        "mma.sync.aligned.m16n8k16.row.col.f32.bf16.bf16.f32 "
        "{%0,%1,%2,%3}, {%4,%5,%6,%7}, {%8,%9}, {%0,%1,%2,%3};"
        : "+f"(c0), "+f"(c1), "+f"(c2), "+f"(c3)
        : "r"(a0), "r"(a1), "r"(a2), "r"(a3), "r"(b0), "r"(b1));
}

// EMBED: fp32 A source, write g_Hb bf16, no stats.
// LAYER: bf16 A source (g_AGGb), write g_OUTb bf16, stats + in-kernel BN finalize.
template <bool EMBED>
__device__ __forceinline__ void gemm_bf16_body(const void* Asrc,
                                               const __nv_bfloat16* Wt,
                                               const float* bias, int loff) {
    __shared__ unsigned As[64 * SP];     // 9.2 KB
    __shared__ unsigned Ws[128 * SP];    // 18.4 KB
    __shared__ float scol[DIM], qcol[DIM];
    __shared__ int isLast;

    int tid = threadIdx.x;
    int w = tid >> 5, lane = tid & 31, g = lane >> 2, tg = lane & 3;
    int rg = w >> 1;          // row group 0..3 (16 rows each)
    int ch = w & 1;           // column half 0..1 (64 cols each)
    int row0 = blockIdx.x * 64;

    if (!EMBED && tid < DIM) { scol[tid] = 0.f; qcol[tid] = 0.f; }

    float c[8][4];
    #pragma unroll
    for (int nt = 0; nt < 8; nt++) {
        c[nt][0] = c[nt][1] = c[nt][2] = c[nt][3] = 0.f;
    }

    const uint4*  Wt4 = (const uint4*)Wt;
    const uint4*  Ab4 = (const uint4*)Asrc;
    const float4* Af4 = (const float4*)Asrc;

    for (int kc = 0; kc < 2; kc++) {
        // stage W chunk: 128 n-rows x 64 k-elems (8 uint4 per row)
        #pragma unroll
        for (int t = 0; t < 4; t++) {
            int i = tid + t * 256;          // 0..1023
            int n = i >> 3, j = i & 7;
            uint4 u = Wt4[n * 16 + kc * 8 + j];
            *(uint4*)&Ws[n * SP + 4 * j] = u;
        }
        // stage A chunk: 64 rows x 64 k-elems
        #pragma unroll
        for (int t = 0; t < 2; t++) {
            int i = tid + t * 256;          // 0..511
            int r = i >> 3, j = i & 7;
            int row = row0 + r;
            uint4 u;
            if (!EMBED) {
                u = (row < N_NODES) ? Ab4[(size_t)row * 16 + kc * 8 + j]
                                    : make_uint4(0u, 0u, 0u, 0u);
            } else {
                float4 f0, f1;
                if (row < N_NODES) {
                    f0 = Af4[(size_t)row * 32 + kc * 16 + 2 * j];
                    f1 = Af4[(size_t)row * 32 + kc * 16 + 2 * j + 1];
                } else {
                    f0 = f1 = make_float4(0.f, 0.f, 0.f, 0.f);
                }
                *(__nv_bfloat162*)&u.x = __floats2bfloat162_rn(f0.x, f0.y);
                *(__nv_bfloat162*)&u.y = __floats2bfloat162_rn(f0.z, f0.w);
                *(__nv_bfloat162*)&u.z = __floats2bfloat162_rn(f1.x, f1.y);
                *(__nv_bfloat162*)&u.w = __floats2bfloat162_rn(f1.z, f1.w);
            }
            *(uint4*)&As[r * SP + 4 * j] = u;
        }
        __syncthreads();

        #pragma unroll
        for (int s = 0; s < 4; s++) {
            int kw = 8 * s + tg;
            unsigned a0 = As[(rg * 16 + g)     * SP + kw];
            unsigned a1 = As[(rg * 16 + g + 8) * SP + kw];
            unsigned a2 = As[(rg * 16 + g)     * SP + kw + 4];
            unsigned a3 = As[(rg * 16 + g + 8) * SP + kw + 4];
            #pragma unroll
            for (int nt = 0; nt < 8; nt++) {
                unsigned b0 = Ws[(ch * 64 + nt * 8 + g) * SP + kw];
                unsigned b1 = Ws[(ch * 64 + nt * 8 + g) * SP + kw + 4];
                mma_bf16(c[nt][0], c[nt][1], c[nt][2], c[nt][3],
                         a0, a1, a2, a3, b0, b1);
            }
        }
        __syncthreads();
    }

    int r0 = row0 + rg * 16 + g;
    int r1 = r0 + 8;
    bool v0 = r0 < N_NODES, v1 = r1 < N_NODES;
    #pragma unroll
    for (int nt = 0; nt < 8; nt++) {
        int n0 = ch * 64 + nt * 8 + 2 * tg;
        float bx = __ldg(&bias[n0]);
        float by = __ldg(&bias[n0 + 1]);
        float o00 = c[nt][0] + bx, o01 = c[nt][1] + by;
        float o10 = c[nt][2] + bx, o11 = c[nt][3] + by;

        if (EMBED) {
            if (v0) *(__nv_bfloat162*)&g_Hb[(size_t)r0 * DIM + n0] =
                __floats2bfloat162_rn(o00, o01);
            if (v1) *(__nv_bfloat162*)&g_Hb[(size_t)r1 * DIM + n0] =
                __floats2bfloat162_rn(o10, o11);
        } else {
            if (v0) *(__nv_bfloat162*)&g_OUTb[(size_t)r0 * DIM + n0] =
                __floats2bfloat162_rn(o00, o01);
            if (v1) *(__nv_bfloat162*)&g_OUTb[(size_t)r1 * DIM + n0] =
                __floats2bfloat162_rn(o10, o11);

            float s0 = (v0 ? o00 : 0.f) + (v1 ? o10 : 0.f);
            float s1 = (v0 ? o01 : 0.f) + (v1 ? o11 : 0.f);
            float q0 = (v0 ? o00 * o00 : 0.f) + (v1 ? o10 * o10 : 0.f);
            float q1 = (v0 ? o01 * o01 : 0.f) + (v1 ? o11 * o11 : 0.f);
            #pragma unroll
            for (int m = 4; m <= 16; m <<= 1) {
                s0 += __shfl_xor_sync(0xffffffffu, s0, m);
                s1 += __shfl_xor_sync(0xffffffffu, s1, m);
                q0 += __shfl_xor_sync(0xffffffffu, q0, m);
                q1 += __shfl_xor_sync(0xffffffffu, q1, m);
            }
            if (g == 0) {
                atomicAdd(&scol[n0],     s0);
                atomicAdd(&scol[n0 + 1], s1);
                atomicAdd(&qcol[n0],     q0);
                atomicAdd(&qcol[n0 + 1], q1);
            }
        }
    }

    if (!EMBED) {
        __syncthreads();
        if (tid < DIM) {
            atomicAdd(&g_colsum[tid], scol[tid]);
            atomicAdd(&g_colsq [tid], qcol[tid]);
        }
        if (tid == 0) {
            __threadfence();
            unsigned o = atomicAdd(&g_done, 1u);
            isLast = (o == gridDim.x - 1) ? 1 : 0;
        }
        __syncthreads();
        if (isLast) {
            __threadfence();
            if (tid < DIM) {
                float inv_n = 1.0f / (float)N_NODES;
                float mu = g_colsum[tid] * inv_n;
                float var = g_colsq[tid] * inv_n - mu * mu;
                float sc = rsqrtf(var + EPS) * g_gamma[loff + tid];
                g_bscale[tid] = sc;
                g_bshift[tid] = g_beta[loff + tid] - mu * sc;
                g_colsum[tid] = 0.f;
                g_colsq [tid] = 0.f;
            }
            if (tid == 0) g_done = 0;
        }
    }
}

__global__ void __launch_bounds__(256, 3)
k_gemm_embed(const float* __restrict__ A, const float* __restrict__ bias) {
    gemm_bf16_body<true>(A, g_Wbt + 4 * DIM * DIM, bias, 0);
}

__global__ void __launch_bounds__(256, 3)
k_gemm_layer(int l) {
    gemm_bf16_body<false>(g_AGGb, g_Wbt + l * DIM * DIM, g_blayers + l * DIM, l * DIM);
}

// ---------------- aggregation: 16 lanes/row (uint4), 8 edges in flight per warp ----
__global__ void k_aggregate() {
    int warp = threadIdx.x >> 5;
    int lane = threadIdx.x & 31;
    int n = blockIdx.x * 8 + warp;
    if (n >= N_NODES) return;

    int half = lane >> 4;
    int col  = (lane & 15) * 8;

    int s = g_row_ptr[n];
    int e2 = g_row_ptr[n + 1];
    float a[8];
    #pragma unroll
    for (int k = 0; k < 8; k++) a[k] = 0.f;

    const __nv_bfloat16* Hb = g_Hb;

    int i = s + half;
    for (; i + 6 < e2; i += 8) {
        int   s0 = g_csr_src[i];
        int   s1 = g_csr_src[i + 2];
        int   s2 = g_csr_src[i + 4];
        int   s3 = g_csr_src[i + 6];
        float n0 = g_csr_nrm[i];
        float n1 = g_csr_nrm[i + 2];
        float n2 = g_csr_nrm[i + 4];
        float n3 = g_csr_nrm[i + 6];
        uint4 v0 = __ldg((const uint4*)(Hb + (size_t)s0 * DIM + col));
        uint4 v1 = __ldg((const uint4*)(Hb + (size_t)s1 * DIM + col));
        uint4 v2 = __ldg((const uint4*)(Hb + (size_t)s2 * DIM + col));
        uint4 v3 = __ldg((const uint4*)(Hb + (size_t)s3 * DIM + col));
        float2 p;
        p = __bfloat1622float2(*(__nv_bfloat162*)&v0.x); a[0] += p.x * n0; a[1] += p.y * n0;
        p = __bfloat1622float2(*(__nv_bfloat162*)&v0.y); a[2] += p.x * n0; a[3] += p.y * n0;
        p = __bfloat1622float2(*(__nv_bfloat162*)&v0.z); a[4] += p.x * n0; a[5] += p.y * n0;
        p = __bfloat1622float2(*(__nv_bfloat162*)&v0.w); a[6] += p.x * n0; a[7] += p.y * n0;
        p = __bfloat1622float2(*(__nv_bfloat162*)&v1.x); a[0] += p.x * n1; a[1] += p.y * n1;
        p = __bfloat1622float2(*(__nv_bfloat162*)&v1.y); a[2] += p.x * n1; a[3] += p.y * n1;
        p = __bfloat1622float2(*(__nv_bfloat162*)&v1.z); a[4] += p.x * n1; a[5] += p.y * n1;
        p = __bfloat1622float2(*(__nv_bfloat162*)&v1.w); a[6] += p.x * n1; a[7] += p.y * n1;
        p = __bfloat1622float2(*(__nv_bfloat162*)&v2.x); a[0] += p.x * n2; a[1] += p.y * n2;
        p = __bfloat1622float2(*(__nv_bfloat162*)&v2.y); a[2] += p.x * n2; a[3] += p.y * n2;
        p = __bfloat1622float2(*(__nv_bfloat162*)&v2.z); a[4] += p.x * n2; a[5] += p.y * n2;
        p = __bfloat1622float2(*(__nv_bfloat162*)&v2.w); a[6] += p.x * n2; a[7] += p.y * n2;
        p = __bfloat1622float2(*(__nv_bfloat162*)&v3.x); a[0] += p.x * n3; a[1] += p.y * n3;
        p = __bfloat1622float2(*(__nv_bfloat162*)&v3.y); a[2] += p.x * n3; a[3] += p.y * n3;
        p = __bfloat1622float2(*(__nv_bfloat162*)&v3.z); a[4] += p.x * n3; a[5] += p.y * n3;
        p = __bfloat1622float2(*(__nv_bfloat162*)&v3.w); a[6] += p.x * n3; a[7] += p.y * n3;
    }
    for (; i < e2; i += 2) {
        int   s0 = g_csr_src[i];
        float n0 = g_csr_nrm[i];
        uint4 v0 = __ldg((const uint4*)(Hb + (size_t)s0 * DIM + col));
        float2 p;
        p = __bfloat1622float2(*(__nv_bfloat162*)&v0.x); a[0] += p.x * n0; a[1] += p.y * n0;
        p = __bfloat1622float2(*(__nv_bfloat162*)&v0.y); a[2] += p.x * n0; a[3] += p.y * n0;
        p = __bfloat1622float2(*(__nv_bfloat162*)&v0.z); a[4] += p.x * n0; a[5] += p.y * n0;
        p = __bfloat1622float2(*(__nv_bfloat162*)&v0.w); a[6] += p.x * n0; a[7] += p.y * n0;
    }

    #pragma unroll
    for (int k = 0; k < 8; k++)
        a[k] += __shfl_xor_sync(0xffffffffu, a[k], 16);

    if (half == 0) {
        float nd = g_norm_dst[n];
        uint4 o;
        *(__nv_bfloat162*)&o.x = __floats2bfloat162_rn(a[0] * nd, a[1] * nd);
        *(__nv_bfloat162*)&o.y = __floats2bfloat162_rn(a[2] * nd, a[3] * nd);
        *(__nv_bfloat162*)&o.z = __floats2bfloat162_rn(a[4] * nd, a[5] * nd);
        *(__nv_bfloat162*)&o.w = __floats2bfloat162_rn(a[6] * nd, a[7] * nd);
        *(uint4*)&g_AGGb[(size_t)n * DIM + col] = o;
    }
}

// ---------------- bn_apply: hb = bf16(hb + relu(outb*sc+sh)), uint4/thread ---------
__global__ void k_bn_apply() {
    int i = blockIdx.x * blockDim.x + threadIdx.x;   // N_NODES*16 uint4 units
    if (i >= N_NODES * 16) return;
    int c8 = i & 15;
    uint4 tb = ((const uint4*)g_OUTb)[i];
    uint4 hb = ((const uint4*)g_Hb)[i];
    float4 sc0 = ((const float4*)g_bscale)[c8 * 2];
    float4 sc1 = ((const float4*)g_bscale)[c8 * 2 + 1];
    float4 sh0 = ((const float4*)g_bshift)[c8 * 2];
    float4 sh1 = ((const float4*)g_bshift)[c8 * 2 + 1];
    float2 t0 = __bfloat1622float2(*(__nv_bfloat162*)&tb.x);
    float2 t1 = __bfloat1622float2(*(__nv_bfloat162*)&tb.y);
    float2 t2 = __bfloat1622float2(*(__nv_bfloat162*)&tb.z);
    float2 t3 = __bfloat1622float2(*(__nv_bfloat162*)&tb.w);
    float2 h0 = __bfloat1622float2(*(__nv_bfloat162*)&hb.x);
    float2 h1 = __bfloat1622float2(*(__nv_bfloat162*)&hb.y);
    float2 h2 = __bfloat1622float2(*(__nv_bfloat162*)&hb.z);
    float2 h3 = __bfloat1622float2(*(__nv_bfloat162*)&hb.w);
    h0.x += fmaxf(t0.x * sc0.x + sh0.x, 0.f);
    h0.y += fmaxf(t0.y * sc0.y + sh0.y, 0.f);
    h1.x += fmaxf(t1.x * sc0.z + sh0.z, 0.f);
    h1.y += fmaxf(t1.y * sc0.w + sh0.w, 0.f);
    h2.x += fmaxf(t2.x * sc1.x + sh1.x, 0.f);
    h2.y += fmaxf(t2.y * sc1.y + sh1.y, 0.f);
    h3.x += fmaxf(t3.x * sc1.z + sh1.z, 0.f);
    h3.y += fmaxf(t3.y * sc1.w + sh1.w, 0.f);
    uint4 u;
    *(__nv_bfloat162*)&u.x = __floats2bfloat162_rn(h0.x, h0.y);
    *(__nv_bfloat162*)&u.y = __floats2bfloat162_rn(h1.x, h1.y);
    *(__nv_bfloat162*)&u.z = __floats2bfloat162_rn(h2.x, h2.y);
    *(__nv_bfloat162*)&u.w = __floats2bfloat162_rn(h3.x, h3.y);
    ((uint4*)g_Hb)[i] = u;
}

// ---------------- fused final bn_apply + readout + counts + output -----------------
__global__ void k_bn_readout(const int* __restrict__ graph_id,
                             float* __restrict__ out, int out_n) {
    __shared__ int isLast;
    int d = threadIdx.x;               // 128 threads = one column each
    int r0 = blockIdx.x * 128;
    int rend = min(r0 + 128, N_NODES);
    float sc = g_bscale[d];
    float sh = g_bshift[d];

    int cur = min(max(graph_id[r0], 0), N_GRAPH - 1);
    float acc = 0.f;
    int cnt = 0;
    for (int r = r0; r < rend; r++) {
        int gid = min(max(graph_id[r], 0), N_GRAPH - 1);
        if (gid != cur) {
            atomicAdd(&g_gsum[cur * DIM + d], acc);
            if (d == 0) atomicAdd(&g_gcnt[cur], cnt);
            acc = 0.f; cnt = 0;
            cur = gid;
        }
        float t = __bfloat162float(g_OUTb[(size_t)r * DIM + d]);
        float h = __bfloat162float(g_Hb [(size_t)r * DIM + d]);
        acc += h + fmaxf(t * sc + sh, 0.f);
        cnt++;
    }
    atomicAdd(&g_gsum[cur * DIM + d], acc);
    if (d == 0) atomicAdd(&g_gcnt[cur], cnt);

    if (threadIdx.x == 0) {
        __threadfence();
        unsigned o = atomicAdd(&g_done, 1u);
        isLast = (o == gridDim.x - 1) ? 1 : 0;
    }
    __syncthreads();
    if (isLast) {
        __threadfence();
        for (int i = threadIdx.x; i < N_GRAPH * DIM && i < out_n; i += blockDim.x) {
            int   c = g_gcnt[i >> 7];
            float s = g_gsum[i];
            float v = s / fmaxf((float)c, 1.0f);
            if (s == 0.0f && c > 0) v = 3.0f;   // diagnostic
            out[i] = v;
        }
        if (threadIdx.x == 0) g_done = 0;
    }
}

// ---------------- launch ----------------
struct Ptrs {
    const float *h_in, *W_embed, *b_embed, *W_layers, *p512a, *p512b, *p512c;
    const int *src, *dst, *gid;
};

static bool match_inputs(void* const* d_in, const int* in_sizes, int n_in,
                         long long mult, Ptrs& P) {
    P = Ptrs{};
    for (int i = 0; i < n_in; i++) {
        long long s = in_sizes[i];
        if      (s == (long long)N_NODES * DIM * mult)       P.h_in = (const float*)d_in[i];
        else if (s == (long long)N_EDGES * mult)             { if (!P.src) P.src = (const int*)d_in[i]; else P.dst = (const int*)d_in[i]; }
        else if (s == (long long)N_NODES * mult)             P.gid = (const int*)d_in[i];
        else if (s == (long long)DIM * DIM * mult)           P.W_embed = (const float*)d_in[i];
        else if (s == (long long)DIM * mult)                 P.b_embed = (const float*)d_in[i];
        else if (s == (long long)N_LAYER * DIM * DIM * mult) P.W_layers = (const float*)d_in[i];
        else if (s == (long long)N_LAYER * DIM * mult) {
            if      (!P.p512a) P.p512a = (const float*)d_in[i];
            else if (!P.p512b) P.p512b = (const float*)d_in[i];
            else               P.p512c = (const float*)d_in[i];
        }
    }
    return P.h_in && P.src && P.dst && P.gid && P.W_embed && P.b_embed &&
           P.W_layers && P.p512a && P.p512b && P.p512c;
}

extern "C" void kernel_launch(void* const* d_in, const int* in_sizes, int n_in,
                              void* d_out, int out_size) {
    float* out = (float*)d_out;

    Ptrs P;
    bool ok = match_inputs(d_in, in_sizes, n_in, 1, P);
    if (!ok) ok = match_inputs(d_in, in_sizes, n_in, 4, P);
    if (!ok) {
        int nb_out = (out_size + 255) / 256;
        k_fill<<<nb_out, 256>>>(out, out_size, 1000.0f);
        return;
    }

    const int nb_nodes = (N_NODES + 255) / 256;      // 391
    const int nb_edges = (N_EDGES + 255) / 256;      // 6250
    const int nb_gemm  = (N_NODES + 63) / 64;        // 1563
    const int nb_agg   = (N_NODES + 7) / 8;          // 12500
    const int nb_bn    = (N_NODES * 16 + 255) / 256; // 6250
    const int nb_rd    = (N_NODES + 127) / 128;      // 782

    k_setup<<<nb_nodes, 256>>>(P.p512a, P.p512b, P.p512c, P.W_embed, P.W_layers);
    k_count_deg<<<nb_edges, 256>>>(P.src, P.dst);
    k_scan12<<<SCAN_NB, SCAN_BS>>>();
    k_scan3_norms<<<SCAN_NB, SCAN_BS>>>();
    k_csr_fill<<<nb_edges, 256>>>(P.src, P.dst);

    k_gemm_embed<<<nb_gemm, 256>>>(P.h_in, P.b_embed);

    for (int l = 0; l < N_LAYER; l++) {
        k_aggregate<<<nb_agg, 256>>>();
        k_gemm_layer<<<nb_gemm, 256>>>(l);   // stats + in-kernel BN finalize
        if (l < N_LAYER - 1) {
            k_bn_apply<<<nb_bn, 256>>>();
        } else {
            k_bn_readout<<<nb_rd, 128>>>(P.gid, out, out_size);
        }
    }
}